// round 17
// baseline (speedup 1.0000x reference)
#include <cuda_runtime.h>
#include <cuda_bf16.h>
#include <math.h>
#include <stdint.h>

#define AN 4096
#define CN 8
#define FN 64
#define NTHREADS 256
#define DIST_BLOCKS 1024

// ---------------- device scratch (no allocation allowed) --------------------
__device__ float          g_xn[CN * AN * FN];   // [c][a][f] normalized fp32
__device__ __nv_bfloat16  g_xp[CN * AN * 64];   // [c][a][f] bf16 (screen)
__device__ ulonglong2     g_q4[CN * AN * 4];    // row-pass partial top2 [c][a][jq]
__device__ uint32_t       g_cols[CN * 32 * 64 * 128]; // col-pass top1 [c][blk][slot][col]
__device__ float          g_partial[DIST_BLOCKS];
__device__ unsigned int   g_done;

// ---------------- PTX helpers (generic sm_80+ ISA only) ---------------------
static __device__ __forceinline__ uint32_t smem_u32(const void* p) {
    uint32_t a;
    asm("{ .reg .u64 t; cvta.to.shared.u64 t, %1; cvt.u32.u64 %0, t; }"
        : "=r"(a) : "l"(p));
    return a;
}

#define CP16(dst, src) \
    asm volatile("cp.async.cg.shared.global [%0], [%1], 16;" :: "r"(dst), "l"(src))
#define CP_COMMIT() asm volatile("cp.async.commit_group;" ::: "memory")
#define CP_WAIT0()  asm volatile("cp.async.wait_group 0;" ::: "memory")

static __device__ __forceinline__ void ldsm_x4(uint32_t* d, uint32_t addr) {
    asm volatile("ldmatrix.sync.aligned.m8n8.x4.shared.b16 {%0,%1,%2,%3}, [%4];"
                 : "=r"(d[0]), "=r"(d[1]), "=r"(d[2]), "=r"(d[3]) : "r"(addr));
}

static __device__ __forceinline__ void mma_bf16(float* c, const uint32_t* a,
                                                const uint32_t* b) {
    asm volatile(
        "mma.sync.aligned.m16n8k16.row.col.f32.bf16.bf16.f32 "
        "{%0,%1,%2,%3}, {%4,%5,%6,%7}, {%8,%9}, {%0,%1,%2,%3};"
        : "+f"(c[0]), "+f"(c[1]), "+f"(c[2]), "+f"(c[3])
        : "r"(a[0]), "r"(a[1]), "r"(a[2]), "r"(a[3]), "r"(b[0]), "r"(b[1]));
}

// swizzled byte offset of 16B chunk (r, ch) in a 128-row x 128B bf16 tile
static __device__ __forceinline__ uint32_t swz128(uint32_t r, uint32_t ch) {
    return r * 128u + ((ch ^ (r & 7u)) << 4);
}

// order-preserving float -> u32
static __device__ __forceinline__ uint32_t ordf(float v) {
    uint32_t u = __float_as_uint(v);
    return (u & 0x80000000u) ? ~u : (u | 0x80000000u);
}

// packed (ord(val), 4095-idx): u64-max = (max value, then min index)
static __device__ __forceinline__ unsigned long long pack_key(float v, int idx) {
    return ((unsigned long long)ordf(v) << 32) | (uint32_t)(4095 - idx);
}

// top-2 merge of two sorted (k1>=k2) pairs over disjoint candidate sets
static __device__ __forceinline__ void merge2(unsigned long long& a1,
                                              unsigned long long& a2,
                                              unsigned long long b1,
                                              unsigned long long b2) {
    if (b1 > a1) { a2 = (a1 > b2) ? a1 : b2; a1 = b1; }
    else         { a2 = (a2 > b1) ? a2 : b1; }
}

// ---------------------------------------------------------------------------
// Kernel 1: normalize rows -> fp32 (c-major) + bf16 row; reset g_done
// ---------------------------------------------------------------------------
__global__ void k_normalize(const float* __restrict__ x) {
    int gtid = blockIdx.x * blockDim.x + threadIdx.x;
    if (gtid == 0) g_done = 0;
    int warp = gtid >> 5;
    int lane = threadIdx.x & 31;
    if (warp >= AN * CN) return;
    int a = warp / CN;
    int c = warp % CN;
    const float2* row = (const float2*)(x + ((size_t)a * CN + c) * FN);
    float2 v = row[lane];
    float ss = v.x * v.x + v.y * v.y;
    #pragma unroll
    for (int o = 16; o > 0; o >>= 1) ss += __shfl_xor_sync(0xffffffffu, ss, o);
    float inv = 1.0f / fmaxf(sqrtf(ss), 1e-6f);
    float nx = v.x * inv, ny = v.y * inv;

    float2* dst = (float2*)(g_xn + ((size_t)c * AN + a) * FN);
    dst[lane] = make_float2(nx, ny);

    __nv_bfloat162 h2;
    h2.x = __float2bfloat16(nx);
    h2.y = __float2bfloat16(ny);
    ((__nv_bfloat162*)(g_xp + ((size_t)c * AN + a) * 64))[lane] = h2;
}

// ---------------------------------------------------------------------------
// Kernel 2: symmetric-triangle bf16 screening GEMM (spill-free fold).
// Job = (row-block ib, strip of <=8 col tiles j>=ib). Row top-2 in regs
// (indices packed 16+16); col top-1 per column staged as u32 keys, computed
// cs-outer with a single scalar running max (no live array -> regs <= 128).
// ---------------------------------------------------------------------------
#define SM_A    0
#define SM_B0   16384
#define SM_B1   32768
#define SM_RED  49152      // 128 rows x 4 warps x 16B = 8 KB
#define SMEM_BYTES 57344

extern __shared__ __align__(1024) uint8_t dsm[];

__global__ __launch_bounds__(NTHREADS, 2) void k_screen() {
    uint32_t sb = smem_u32(dsm);
    int tid = threadIdx.x;
    int lane = tid & 31;
    int wid = tid >> 5;
    int wm = wid >> 2;
    int wn = wid & 3;
    int c = blockIdx.y;

    // decode job (ib, jq) from blockIdx.x in [0, 80)
    int bx = blockIdx.x;
    int ib = 0, jq = 0;
    {
        int cum = 0;
        #pragma unroll 1
        for (int i = 0; i < 32; i++) {
            int n = (32 - i + 7) >> 3;
            if (bx < cum + n) { ib = i; jq = bx - cum; break; }
            cum += n;
        }
    }
    int j0 = ib + jq * 8;
    int nt = min(32, j0 + 8) - j0;   // tiles in this job (1..8)
    int row0 = ib * 128;

    const char* xc = (const char*)(g_xp + (size_t)c * AN * 64);  // 128B rows

    uint32_t a_rl = (uint32_t)((lane & 7) + ((lane >> 3) & 1) * 8);
    uint32_t a_cs = (uint32_t)(lane >> 4);
    uint32_t b_nl = (uint32_t)((lane & 7) + (lane >> 4) * 8);
    uint32_t b_cs = (uint32_t)((lane >> 3) & 1);
    uint32_t arow = (uint32_t)(wm * 64);

    float    rv1[8], rv2[8];
    uint32_t ri12[8];                // (idx1 << 16) | idx2
    #pragma unroll
    for (int s = 0; s < 8; s++) { rv1[s] = -3.0f; rv2[s] = -4.0f; ri12[s] = 0u; }

    float acc[4][4][4];

    // fold tile pt (col-block j=pt). DIAG only for the diagonal tile.
    auto fold = [&](int pt, bool DIAG) {
        // ---- row pass: per-slot tile max -> one top-2 insert ----
        #pragma unroll
        for (int mi = 0; mi < 4; mi++) {
            #pragma unroll
            for (int hh = 0; hh < 2; hh++) {
                int s = mi * 2 + hh;
                int lrow = wm * 64 + mi * 16 + (lane >> 2) + hh * 8;
                float bv = -5.0f;
                int   bc = 0;
                #pragma unroll
                for (int ni = 0; ni < 4; ni++) {
                    #pragma unroll
                    for (int q = 0; q < 2; q++) {
                        float v = acc[mi][ni][hh * 2 + q];
                        if (DIAG) {
                            int cc = wn * 32 + ni * 8 + (lane & 3) * 2 + q;
                            v = (cc == lrow) ? -2.0f : v;
                        }
                        int cd = ni * 2 + q;          // ascending col in thread
                        bool g = v > bv;              // strict > = first index
                        bv = g ? v : bv;
                        bc = g ? cd : bc;
                    }
                }
                uint32_t idx = (uint32_t)(pt * 128 + wn * 32 +
                                          (bc >> 1) * 8 + (lane & 3) * 2 + (bc & 1));
                bool g1 = bv > rv1[s];
                bool g2 = bv > rv2[s];
                uint32_t c1 = (idx << 16) | (ri12[s] >> 16);
                uint32_t c2 = (ri12[s] & 0xFFFF0000u) | idx;
                ri12[s] = g1 ? c1 : (g2 ? c2 : ri12[s]);
                rv2[s]  = g1 ? rv1[s] : (g2 ? bv : rv2[s]);
                rv1[s]  = g1 ? bv : rv1[s];
            }
        }
        // ---- col pass: cs-outer, scalar running key (no live array) ----
        if (!DIAG) {
            uint32_t lc = (uint32_t)(lane >> 2);
            uint32_t* base = g_cols +
                (((size_t)c * 32 + pt) * 64 + (2 * ib + wm)) * 128;
            #pragma unroll
            for (int cs = 0; cs < 8; cs++) {
                int ni = cs >> 1, q = cs & 1;
                uint32_t k = 0u;
                #pragma unroll
                for (int mi = 0; mi < 4; mi++) {
                    #pragma unroll
                    for (int hh = 0; hh < 2; hh++) {
                        uint32_t key =
                            (ordf(acc[mi][ni][hh * 2 + q]) & 0xFFFFFFC0u) |
                            (uint32_t)((hh << 5) | (mi << 3)) | lc;
                        k = (key > k) ? key : k;
                    }
                }
                uint32_t o;
                o = __shfl_down_sync(0xffffffffu, k, 16); k = (o > k) ? o : k;
                o = __shfl_down_sync(0xffffffffu, k, 8);  k = (o > k) ? o : k;
                o = __shfl_down_sync(0xffffffffu, k, 4);  k = (o > k) ? o : k;
                if (lane < 4)
                    base[wn * 32 + ni * 8 + lane * 2 + q] = k;
            }
        }
    };

    // ---- prologue: A tile + B tile j0 (one cp.async group) ----
    #pragma unroll
    for (int u = 0; u < 4; u++) {
        int s = tid + u * NTHREADS;          // 0..1023
        uint32_t r = (uint32_t)(s >> 3), ch = (uint32_t)(s & 7);
        CP16(sb + SM_A  + swz128(r, ch), xc + (size_t)(row0 + r) * 128 + ch * 16);
        CP16(sb + SM_B0 + swz128(r, ch), xc + (size_t)(j0 * 128 + r) * 128 + ch * 16);
    }
    CP_COMMIT();

    #pragma unroll 1
    for (int tt = 0; tt < nt; tt++) {
        int j = j0 + tt;
        CP_WAIT0();
        __syncthreads();

        if (tt + 1 < nt) {   // prefetch next B into the other buffer
            uint32_t bufn = sb + ((tt & 1) ? SM_B0 : SM_B1);
            const char* bsrc = xc + (size_t)(j + 1) * 128 * 128;
            #pragma unroll
            for (int u = 0; u < 4; u++) {
                int s = tid + u * NTHREADS;
                uint32_t r = (uint32_t)(s >> 3), ch = (uint32_t)(s & 7);
                CP16(bufn + swz128(r, ch), bsrc + (size_t)r * 128 + ch * 16);
            }
            CP_COMMIT();
        }

        // deferred epilogue of tile j-1 — overlaps the HMMA issue below
        if (tt > 0) {
            if (j - 1 == ib) fold(j - 1, true);
            else             fold(j - 1, false);
        }

        // ---- MMA tile j ----
        #pragma unroll
        for (int mi = 0; mi < 4; mi++)
            #pragma unroll
            for (int ni = 0; ni < 4; ni++)
                #pragma unroll
                for (int q = 0; q < 4; q++) acc[mi][ni][q] = 0.0f;

        uint32_t bufc = sb + ((tt & 1) ? SM_B1 : SM_B0);
        #pragma unroll
        for (int ks = 0; ks < 4; ks++) {
            uint32_t kc = (uint32_t)(ks * 2);
            uint32_t af[4][4], bf[2][4];
            #pragma unroll
            for (int mi = 0; mi < 4; mi++)
                ldsm_x4(af[mi], sb + SM_A + swz128(arow + (uint32_t)(mi * 16) + a_rl, kc + a_cs));
            #pragma unroll
            for (int nh = 0; nh < 2; nh++)
                ldsm_x4(bf[nh], bufc + swz128((uint32_t)(wn * 32 + nh * 16) + b_nl, kc + b_cs));
            #pragma unroll
            for (int mi = 0; mi < 4; mi++)
                #pragma unroll
                for (int ni = 0; ni < 4; ni++)
                    mma_bf16(acc[mi][ni], af[mi], &bf[ni >> 1][(ni & 1) * 2]);
        }
    }

    // fold the last tile of this job
    {
        int jl = j0 + nt - 1;
        if (jl == ib) fold(jl, true);
        else          fold(jl, false);
    }

    // ---- row top-2 reduce: quad -> smem -> 4 wn warps -> g_q4 slot jq ----
    __syncthreads();
    ulonglong2* red = (ulonglong2*)(dsm + SM_RED);
    #pragma unroll
    for (int mi = 0; mi < 4; mi++) {
        #pragma unroll
        for (int hh = 0; hh < 2; hh++) {
            int s = mi * 2 + hh;
            unsigned long long k1 = pack_key(rv1[s], (int)(ri12[s] >> 16));
            unsigned long long k2 = pack_key(rv2[s], (int)(ri12[s] & 0xFFFFu));
            #pragma unroll
            for (int o = 2; o > 0; o >>= 1) {
                unsigned long long o1 = __shfl_down_sync(0xffffffffu, k1, o, 4);
                unsigned long long o2 = __shfl_down_sync(0xffffffffu, k2, o, 4);
                merge2(k1, k2, o1, o2);
            }
            if ((lane & 3) == 0) {
                int lrow = wm * 64 + mi * 16 + (lane >> 2) + hh * 8;
                red[lrow * 4 + wn] = make_ulonglong2(k1, k2);
            }
        }
    }
    __syncthreads();
    if (tid < 128) {
        ulonglong2 a = red[tid * 4];
        #pragma unroll
        for (int w = 1; w < 4; w++) {
            ulonglong2 b = red[tid * 4 + w];
            merge2(a.x, a.y, b.x, b.y);
        }
        g_q4[((size_t)c * AN + row0 + tid) * 4 + jq] = a;
    }
}

// ---------------------------------------------------------------------------
// Kernel 3: merge row slots + col slots (lane-parallel + xor-butterfly),
// exact fp32 top-2 refine, distance, fused final reduction.
// ---------------------------------------------------------------------------
__global__ void k_dist(float* __restrict__ out) {
    int gwarp  = (blockIdx.x * blockDim.x + threadIdx.x) >> 5;
    int lane   = threadIdx.x & 31;
    int nwarps = (gridDim.x * blockDim.x) >> 5;
    float acc = 0.0f;
    for (int item = gwarp; item < CN * AN; item += nwarps) {
        int c = item >> 12;
        int a = item & 4095;
        int k = a >> 7;          // row's block
        int r = a & 127;
        int njq = (32 - k + 7) >> 3;

        unsigned long long A1 = 0ull, A2 = 0ull;
        if (lane < njq) {        // disjoint: one row slot per lane
            ulonglong2 kk = g_q4[(size_t)item * 4 + lane];
            A1 = kk.x; A2 = kk.y;
        }
        int ns = 2 * k;          // col slots from tiles (i<k, wm)
        for (int s = lane; s < ns; s += 32) {
            uint32_t key = g_cols[(((size_t)c * 32 + k) * 64 + s) * 128 + r];
            int i = s >> 1, wmm = s & 1;
            int code = key & 63;
            int grow = i * 128 + wmm * 64 + ((code >> 3) & 3) * 16 +
                       (code >> 5) * 8 + (code & 7);
            unsigned long long ck =
                ((unsigned long long)(key & 0xFFFFFFC0u) << 32) |
                (uint32_t)(4095 - grow);
            if (ck > A1) { A2 = A1; A1 = ck; }
            else         { A2 = (A2 > ck) ? A2 : ck; }
        }
        // xor butterfly: partner sets stay disjoint at every level
        #pragma unroll
        for (int o = 16; o > 0; o >>= 1) {
            unsigned long long o1 = __shfl_xor_sync(0xffffffffu, A1, o);
            unsigned long long o2 = __shfl_xor_sync(0xffffffffu, A2, o);
            merge2(A1, A2, o1, o2);
        }

        int iA = 4095 - (int)(uint32_t)(A1 & 0xFFFFFFFFull);
        int iB = 4095 - (int)(uint32_t)(A2 & 0xFFFFFFFFull);
        const float2* pa = (const float2*)(g_xn + (size_t)item * FN);
        const float2* p1 = (const float2*)(g_xn + ((size_t)c * AN + iA) * FN);
        const float2* p2 = (const float2*)(g_xn + ((size_t)c * AN + iB) * FN);
        float2 va = pa[lane], v1 = p1[lane], v2 = p2[lane];
        float s1 = va.x * v1.x + va.y * v1.y;
        float s2 = va.x * v2.x + va.y * v2.y;
        #pragma unroll
        for (int o = 16; o > 0; o >>= 1) {
            s1 += __shfl_xor_sync(0xffffffffu, s1, o);
            s2 += __shfl_xor_sync(0xffffffffu, s2, o);
        }
        bool useA = (s1 > s2) || (s1 == s2 && iA < iB);
        float2 vb = useA ? v1 : v2;
        float dx = va.x - vb.x + 1e-6f;
        float dy = va.y - vb.y + 1e-6f;
        float ss = dx * dx + dy * dy;
        #pragma unroll
        for (int o = 16; o > 0; o >>= 1) ss += __shfl_xor_sync(0xffffffffu, ss, o);
        if (lane == 0) acc -= logf(sqrtf(ss) + 1e-6f);
    }
    __shared__ float wsum[8];
    __shared__ float smf[256];
    if (lane == 0) wsum[threadIdx.x >> 5] = acc;
    __syncthreads();
    if (threadIdx.x == 0) {
        float s = 0.0f;
        #pragma unroll
        for (int i = 0; i < 8; i++) s += wsum[i];
        g_partial[blockIdx.x] = s;
        __threadfence();
        unsigned t = atomicInc(&g_done, 0xFFFFFFFFu);
        wsum[0] = (t == gridDim.x - 1) ? 1.0f : 0.0f;
    }
    __syncthreads();
    if (wsum[0] != 0.0f) {              // last block: deterministic final sum
        float s = 0.0f;
        #pragma unroll
        for (int u = 0; u < DIST_BLOCKS / 256; u++)
            s += g_partial[threadIdx.x + u * 256];
        smf[threadIdx.x] = s;
        __syncthreads();
        for (int st = 128; st > 0; st >>= 1) {
            if (threadIdx.x < st) smf[threadIdx.x] += smf[threadIdx.x + st];
            __syncthreads();
        }
        if (threadIdx.x == 0) out[0] = smf[0] / (float)(CN * AN);
    }
}

// ---------------------------------------------------------------------------
extern "C" void kernel_launch(void* const* d_in, const int* in_sizes, int n_in,
                              void* d_out, int out_size) {
    const float* x = (const float*)d_in[0];
    float* out = (float*)d_out;
    (void)in_sizes; (void)n_in; (void)out_size;

    cudaFuncSetAttribute(k_screen,
                         cudaFuncAttributeMaxDynamicSharedMemorySize, SMEM_BYTES);

    k_normalize<<<(AN * CN) / 8, NTHREADS>>>(x);
    k_screen<<<dim3(80, CN), NTHREADS, SMEM_BYTES>>>();
    k_dist<<<DIST_BLOCKS, NTHREADS>>>(out);
}